// round 1
// baseline (speedup 1.0000x reference)
#include <cuda_runtime.h>
#include <cstdint>

// Problem constants
#define BATCH   8
#define NPTS    16384
#define NPOINT  128
#define NSAMPLE 32
#define C_IN    256
#define C1      259          // 3 + 256
#define C1P     288          // padded to 9*32
#define C_MID   256
#define C_OUT   256
#define R2      0.16f        // f32(0.16): matches jax weak-f64->f32 cast of radius*radius
#define BN_EPS  1e-5f

// ---------------- scratch (device globals; no runtime allocation) ----------------
__device__ int   d_inds[BATCH * NPOINT];                       // FPS indices
__device__ float d_x   [(size_t)BATCH * NPOINT * NSAMPLE * C1P];   // gathered inputs, zero-padded
__device__ float d_h   [(size_t)BATCH * NPOINT * NSAMPLE * C_MID]; // layer1 activations
__device__ float d_w1t [C1P * C_MID];                          // w1 transposed [c][o], zero-padded rows
__device__ float d_w2t [C_MID * C_OUT];                        // w2 transposed [c][o]
__device__ float d_s1[C_MID], d_b1[C_MID], d_s2[C_OUT], d_b2[C_OUT];

// ---------------- prep: transpose weights + fold BN ----------------
__global__ void prep_kernel(const float* __restrict__ w1, const float* __restrict__ w2,
                            const float* __restrict__ g1, const float* __restrict__ be1,
                            const float* __restrict__ m1, const float* __restrict__ v1,
                            const float* __restrict__ g2, const float* __restrict__ be2,
                            const float* __restrict__ m2, const float* __restrict__ v2) {
    int o = threadIdx.x;
    int blk = blockIdx.x;
    if (blk < C1P) {
        int c = blk;
        d_w1t[c * C_MID + o] = (c < C1) ? w1[o * C1 + c] : 0.0f;
        if (blk == 0) {
            float s = g1[o] / sqrtf(v1[o] + BN_EPS);
            d_s1[o] = s;
            d_b1[o] = be1[o] - m1[o] * s;
        } else if (blk == 1) {
            float s = g2[o] / sqrtf(v2[o] + BN_EPS);
            d_s2[o] = s;
            d_b2[o] = be2[o] - m2[o] * s;
        }
    } else {
        int c = blk - C1P;
        d_w2t[c * C_OUT + o] = w2[o * C_MID + c];
    }
}

// ---------------- FPS: one block per batch ----------------
__global__ __launch_bounds__(1024) void fps_kernel(const float* __restrict__ xyz) {
    extern __shared__ float sm[];
    float2* sxy = reinterpret_cast<float2*>(sm);           // 16384 * 8B
    float*  sz  = sm + 2 * NPTS;                           // 16384 * 4B
    __shared__ float rv[32];
    __shared__ int   ri[32];
    __shared__ int   sfar;

    const int b   = blockIdx.x;
    const int tid = threadIdx.x;
    const float* base = xyz + (size_t)b * NPTS * 3;

    for (int i = tid; i < NPTS; i += 1024) {
        float x = base[3 * i], y = base[3 * i + 1], z = base[3 * i + 2];
        sxy[i] = make_float2(x, y);
        sz[i]  = z;
    }
    float dst[16];
#pragma unroll
    for (int p = 0; p < 16; ++p) dst[p] = 1e10f;
    __syncthreads();

    int far = 0;
    for (int j = 0; j < NPOINT; ++j) {
        if (tid == 0) d_inds[b * NPOINT + j] = far;
        float2 cxy = sxy[far];
        float  cz  = sz[far];

        float bv = -1.0f;
        int   bi = 0;
#pragma unroll
        for (int p = 0; p < 16; ++p) {
            int i = tid + (p << 10);
            float2 pxy = sxy[i];
            float  pz  = sz[i];
            // exact: sub, mul, add (no FMA contraction) to match reference fp32 math
            float dx = __fadd_rn(pxy.x, -cxy.x);
            float dy = __fadd_rn(pxy.y, -cxy.y);
            float dz = __fadd_rn(pz,   -cz);
            float d  = __fadd_rn(__fadd_rn(__fmul_rn(dx, dx), __fmul_rn(dy, dy)), __fmul_rn(dz, dz));
            float nd = fminf(dst[p], d);
            dst[p] = nd;
            if (nd > bv) { bv = nd; bi = i; }    // strict > keeps smallest i within thread
        }
        // warp argmax (tie -> smaller index)
#pragma unroll
        for (int off = 16; off > 0; off >>= 1) {
            float ov = __shfl_down_sync(0xffffffffu, bv, off);
            int   oi = __shfl_down_sync(0xffffffffu, bi, off);
            if (ov > bv || (ov == bv && oi < bi)) { bv = ov; bi = oi; }
        }
        if ((tid & 31) == 0) { rv[tid >> 5] = bv; ri[tid >> 5] = bi; }
        __syncthreads();
        if (tid < 32) {
            bv = rv[tid]; bi = ri[tid];
#pragma unroll
            for (int off = 16; off > 0; off >>= 1) {
                float ov = __shfl_down_sync(0xffffffffu, bv, off);
                int   oi = __shfl_down_sync(0xffffffffu, bi, off);
                if (ov > bv || (ov == bv && oi < bi)) { bv = ov; bi = oi; }
            }
            if (tid == 0) sfar = bi;
        }
        __syncthreads();
        far = sfar;
    }
}

// ---------------- ball query + gather: one block per (b, s) ----------------
__global__ __launch_bounds__(256) void bq_gather_kernel(const float* __restrict__ xyz,
                                                        const float* __restrict__ feats) {
    __shared__ int   sidx[NSAMPLE];
    __shared__ float ctr[3];

    const int bs  = blockIdx.x;
    const int b   = bs >> 7;
    const int tid = threadIdx.x;
    const float* xb = xyz + (size_t)b * NPTS * 3;

    if (tid < 32) {
        int ind = d_inds[bs];
        float cx = xb[ind * 3], cy = xb[ind * 3 + 1], cz = xb[ind * 3 + 2];
        if (tid == 0) { ctr[0] = cx; ctr[1] = cy; ctr[2] = cz; }
        int cnt = 0;
        for (int basei = 0; basei < NPTS && cnt < NSAMPLE; basei += 32) {
            int i = basei + tid;
            float dx = __fadd_rn(cx, -xb[i * 3]);
            float dy = __fadd_rn(cy, -xb[i * 3 + 1]);
            float dz = __fadd_rn(cz, -xb[i * 3 + 2]);
            float d2 = __fadd_rn(__fadd_rn(__fmul_rn(dx, dx), __fmul_rn(dy, dy)), __fmul_rn(dz, dz));
            bool pred = d2 < R2;
            unsigned m = __ballot_sync(0xffffffffu, pred);
            int r    = __popc(m & ((1u << tid) - 1u));
            int tot  = __popc(m);
            int take = min(tot, NSAMPLE - cnt);
            if (pred && r < take) sidx[cnt + r] = i;
            cnt += take;
        }
        __syncwarp();
        if (cnt < NSAMPLE) {
            int f = sidx[0];   // always >= 1 hit (centroid itself, d2 = 0)
            for (int pos = cnt + tid; pos < NSAMPLE; pos += 32) sidx[pos] = f;
        }
    }
    __syncthreads();

    const float* fb = feats + (size_t)b * NPTS * C_IN;
    float* xrow = d_x + (size_t)bs * NSAMPLE * C1P;
    for (int k = 0; k < NSAMPLE; ++k) {
        int p = sidx[k];
        float* row = xrow + k * C1P;
        if (tid < 3)  row[tid] = __fadd_rn(xb[p * 3 + tid], -ctr[tid]);
        row[3 + tid] = fb[(size_t)p * C_IN + tid];
        if (tid < C1P - C1) row[C1 + tid] = 0.0f;   // zero pad columns 259..287
    }
}

// ---------------- GEMM helpers (packed f32x2) ----------------
__device__ __forceinline__ unsigned long long pack_dup(float v) {
    unsigned long long r;
    unsigned b = __float_as_uint(v);
    asm("mov.b64 %0, {%1, %1};" : "=l"(r) : "r"(b));
    return r;
}
__device__ __forceinline__ void fma2(unsigned long long& acc, unsigned long long a, unsigned long long b) {
    asm("fma.rn.f32x2 %0, %1, %2, %0;" : "+l"(acc) : "l"(a), "l"(b));
}

// ---------------- GEMM1: h = bn_relu(x @ w1^T), one block per (b,s) ----------------
__global__ __launch_bounds__(256, 2) void gemm1_kernel() {
    __shared__ float sx[32][33];
    __shared__ float sw[32][256];

    const int bs  = blockIdx.x;
    const int tid = threadIdx.x;
    const int oq  = tid & 31;   // lane: o-pair group
    const int kg  = tid >> 5;   // warp: k group (4 rows)

    unsigned long long acc[4][4];
#pragma unroll
    for (int i = 0; i < 4; ++i)
#pragma unroll
        for (int j = 0; j < 4; ++j) acc[i][j] = 0ull;

    const float* xbase = d_x + (size_t)bs * NSAMPLE * C1P;

    for (int ct = 0; ct < C1P / 32; ++ct) {
        int c0 = ct * 32;
        __syncthreads();
        for (int i = tid; i < 32 * 32; i += 256) {
            int k = i >> 5, c = i & 31;
            sx[k][c] = xbase[k * C1P + c0 + c];
        }
        for (int i = tid; i < 32 * 256; i += 256) {
            int c = i >> 8, o = i & 255;
            sw[c][o] = d_w1t[(c0 + c) * C_MID + o];
        }
        __syncthreads();
#pragma unroll
        for (int c = 0; c < 32; ++c) {
            unsigned long long xd[4];
#pragma unroll
            for (int i = 0; i < 4; ++i) xd[i] = pack_dup(sx[kg * 4 + i][c]);
            const unsigned long long* wrow = reinterpret_cast<const unsigned long long*>(&sw[c][0]);
            unsigned long long wd[4];
#pragma unroll
            for (int j = 0; j < 4; ++j) wd[j] = wrow[j * 32 + oq];  // o = j*64 + oq*2 (+0/1)
#pragma unroll
            for (int i = 0; i < 4; ++i)
#pragma unroll
                for (int j = 0; j < 4; ++j) fma2(acc[i][j], xd[i], wd[j]);
        }
    }

    const size_t hbase = (size_t)bs * NSAMPLE * C_MID;
#pragma unroll
    for (int j = 0; j < 4; ++j) {
        int o = j * 64 + oq * 2;
        float s0 = d_s1[o], s1v = d_s1[o + 1];
        float b0 = d_b1[o], b1v = d_b1[o + 1];
#pragma unroll
        for (int i = 0; i < 4; ++i) {
            float lo = __uint_as_float((unsigned)(acc[i][j] & 0xffffffffull));
            float hi = __uint_as_float((unsigned)(acc[i][j] >> 32));
            lo = fmaxf(fmaf(lo, s0, b0), 0.0f);
            hi = fmaxf(fmaf(hi, s1v, b1v), 0.0f);
            *reinterpret_cast<float2*>(&d_h[hbase + (size_t)(kg * 4 + i) * C_MID + o]) = make_float2(lo, hi);
        }
    }
}

// ---------------- GEMM2 + maxpool: out[b][o][s] = max_k bn_relu(h @ w2^T) ----------------
__global__ __launch_bounds__(256, 2) void gemm2_kernel(float* __restrict__ out) {
    __shared__ float sx[32][33];
    __shared__ float sw[32][256];
    __shared__ float red[8][256];

    const int bs  = blockIdx.x;
    const int tid = threadIdx.x;
    const int oq  = tid & 31;
    const int kg  = tid >> 5;

    unsigned long long acc[4][4];
#pragma unroll
    for (int i = 0; i < 4; ++i)
#pragma unroll
        for (int j = 0; j < 4; ++j) acc[i][j] = 0ull;

    const float* xbase = d_h + (size_t)bs * NSAMPLE * C_MID;

    for (int ct = 0; ct < C_MID / 32; ++ct) {
        int c0 = ct * 32;
        __syncthreads();
        for (int i = tid; i < 32 * 32; i += 256) {
            int k = i >> 5, c = i & 31;
            sx[k][c] = xbase[(size_t)k * C_MID + c0 + c];
        }
        for (int i = tid; i < 32 * 256; i += 256) {
            int c = i >> 8, o = i & 255;
            sw[c][o] = d_w2t[(c0 + c) * C_OUT + o];
        }
        __syncthreads();
#pragma unroll
        for (int c = 0; c < 32; ++c) {
            unsigned long long xd[4];
#pragma unroll
            for (int i = 0; i < 4; ++i) xd[i] = pack_dup(sx[kg * 4 + i][c]);
            const unsigned long long* wrow = reinterpret_cast<const unsigned long long*>(&sw[c][0]);
            unsigned long long wd[4];
#pragma unroll
            for (int j = 0; j < 4; ++j) wd[j] = wrow[j * 32 + oq];
#pragma unroll
            for (int i = 0; i < 4; ++i)
#pragma unroll
                for (int j = 0; j < 4; ++j) fma2(acc[i][j], xd[i], wd[j]);
        }
    }

#pragma unroll
    for (int j = 0; j < 4; ++j) {
        int o = j * 64 + oq * 2;
        float s0 = d_s2[o], s1v = d_s2[o + 1];
        float b0 = d_b2[o], b1v = d_b2[o + 1];
        float m0 = 0.0f, m1 = 0.0f;   // relu output >= 0, so 0 is identity for max
#pragma unroll
        for (int i = 0; i < 4; ++i) {
            float lo = __uint_as_float((unsigned)(acc[i][j] & 0xffffffffull));
            float hi = __uint_as_float((unsigned)(acc[i][j] >> 32));
            lo = fmaxf(fmaf(lo, s0, b0), 0.0f);
            hi = fmaxf(fmaf(hi, s1v, b1v), 0.0f);
            m0 = fmaxf(m0, lo);
            m1 = fmaxf(m1, hi);
        }
        red[kg][o]     = m0;
        red[kg][o + 1] = m1;
    }
    __syncthreads();
    float m = red[0][tid];
#pragma unroll
    for (int r = 1; r < 8; ++r) m = fmaxf(m, red[r][tid]);
    int b = bs >> 7, s = bs & 127;
    out[((size_t)b * C_OUT + tid) * NPOINT + s] = m;
}

// ---------------- launch ----------------
extern "C" void kernel_launch(void* const* d_in, const int* in_sizes, int n_in,
                              void* d_out, int out_size) {
    const float* xyz   = (const float*)d_in[0];
    const float* feats = (const float*)d_in[1];
    const float* w1    = (const float*)d_in[2];
    const float* g1    = (const float*)d_in[3];
    const float* be1   = (const float*)d_in[4];
    const float* m1    = (const float*)d_in[5];
    const float* v1    = (const float*)d_in[6];
    const float* w2    = (const float*)d_in[7];
    const float* g2    = (const float*)d_in[8];
    const float* be2   = (const float*)d_in[9];
    const float* m2    = (const float*)d_in[10];
    const float* v2    = (const float*)d_in[11];
    float* out = (float*)d_out;

    cudaFuncSetAttribute(fps_kernel, cudaFuncAttributeMaxDynamicSharedMemorySize, 3 * NPTS * 4);

    prep_kernel<<<C1P + C_MID, 256>>>(w1, w2, g1, be1, m1, v1, g2, be2, m2, v2);
    fps_kernel<<<BATCH, 1024, 3 * NPTS * 4>>>(xyz);
    bq_gather_kernel<<<BATCH * NPOINT, 256>>>(xyz, feats);
    gemm1_kernel<<<BATCH * NPOINT, 256>>>();
    gemm2_kernel<<<BATCH * NPOINT, 256>>>(out);
}